// round 5
// baseline (speedup 1.0000x reference)
#include <cuda_runtime.h>

// SpikeLoss: delta = outputs - psp(target, tau=5); loss = 0.5*sum(delta^2)
// psp: syn_t = decay*syn_{t-1} + x_t ; y_t = syn_t / tau, scan over T=100
// (contiguous last axis).
//
// One WARP per row. Row = 100 floats = 3 full 32-chunks + 4-tail.
// Each chunk: coalesced 128B warp load + Kogge-Stone inclusive scan of the
// linear recurrence via shfl (5 steps), then carry-in correction
// syn = v + decay^(lane+1)*carry. All global loads are contiguous per warp
// (nL=1-2 lines per LDG vs 32 in the per-thread-row version -> L1tex
// wavefront queue no longer binds).

static constexpr int   T_STEPS = 100;
static constexpr float DECAY   = 0.8f;   // 1 - 1/tau
static constexpr float INV_TAU = 0.2f;

__global__ void zero_out_kernel(float* __restrict__ out) {
    out[0] = 0.0f;
}

// Kogge-Stone scan of syn_i = decay*syn_{i-1} + x_i within a 32-lane chunk.
__device__ __forceinline__ float chunk_scan(float v, int lane) {
    float u;
    u = __shfl_up_sync(0xffffffffu, v, 1);
    if (lane >= 1)  v = fmaf(0.8f, u, v);
    u = __shfl_up_sync(0xffffffffu, v, 2);
    if (lane >= 2)  v = fmaf(0.64f, u, v);
    u = __shfl_up_sync(0xffffffffu, v, 4);
    if (lane >= 4)  v = fmaf(0.4096f, u, v);
    u = __shfl_up_sync(0xffffffffu, v, 8);
    if (lane >= 8)  v = fmaf(0.16777216f, u, v);
    u = __shfl_up_sync(0xffffffffu, v, 16);
    if (lane >= 16) v = fmaf(0.0281474977f, u, v);
    return v;
}

__global__ __launch_bounds__(256)
void spike_loss_kernel(const float* __restrict__ outputs,
                       const float* __restrict__ target,
                       float* __restrict__ out,
                       int n_rows) {
    const int lane   = threadIdx.x & 31;
    const int wid    = threadIdx.x >> 5;
    const int gwarp  = blockIdx.x * (blockDim.x >> 5) + wid;
    const int nwarps = gridDim.x * (blockDim.x >> 5);

    // decay^(lane+1), computed once via binary exponentiation (exact fp32 muls)
    float dp = 1.0f;
    {
        int e = lane + 1;
        float b = DECAY;
        while (e) {
            if (e & 1) dp *= b;
            b *= b;
            e >>= 1;
        }
    }

    float acc = 0.0f;

    for (int row = gwarp; row < n_rows; row += nwarps) {
        const float* __restrict__ tr = target  + (size_t)row * T_STEPS;
        const float* __restrict__ po = outputs + (size_t)row * T_STEPS;

        // Front-batch all 8 loads (coalesced 128B per warp; tail = 16B)
        const bool tail_ok = (lane < 4);
        float t0 = tr[lane];
        float t1 = tr[32 + lane];
        float t2 = tr[64 + lane];
        float t3 = tail_ok ? tr[96 + lane] : 0.0f;
        float o0 = po[lane];
        float o1 = po[32 + lane];
        float o2 = po[64 + lane];
        float o3 = tail_ok ? po[96 + lane] : 0.0f;

        float carry = 0.0f;
        float v, y, d;

        // chunk 0
        v = chunk_scan(t0, lane);                 // carry==0, skip correction
        y = v * INV_TAU; d = o0 - y; acc = fmaf(d, d, acc);
        carry = __shfl_sync(0xffffffffu, v, 31);

        // chunk 1
        v = chunk_scan(t1, lane);
        v = fmaf(dp, carry, v);
        y = v * INV_TAU; d = o1 - y; acc = fmaf(d, d, acc);
        carry = __shfl_sync(0xffffffffu, v, 31);

        // chunk 2
        v = chunk_scan(t2, lane);
        v = fmaf(dp, carry, v);
        y = v * INV_TAU; d = o2 - y; acc = fmaf(d, d, acc);
        carry = __shfl_sync(0xffffffffu, v, 31);

        // chunk 3 (4 valid elements)
        v = chunk_scan(t3, lane);
        v = fmaf(dp, carry, v);
        if (tail_ok) {
            y = v * INV_TAU; d = o3 - y; acc = fmaf(d, d, acc);
        }
    }

    // Warp reduction
    #pragma unroll
    for (int off = 16; off > 0; off >>= 1)
        acc += __shfl_down_sync(0xffffffffu, acc, off);

    __shared__ float warp_sums[8];
    if (lane == 0) warp_sums[wid] = acc;
    __syncthreads();

    if (wid == 0) {
        acc = (lane < (blockDim.x >> 5)) ? warp_sums[lane] : 0.0f;
        #pragma unroll
        for (int off = 4; off > 0; off >>= 1)
            acc += __shfl_down_sync(0xffffffffu, acc, off);
        if (lane == 0)
            atomicAdd(out, 0.5f * acc);
    }
}

extern "C" void kernel_launch(void* const* d_in, const int* in_sizes, int n_in,
                              void* d_out, int out_size) {
    const float* outputs = (const float*)d_in[0];
    const float* target  = (const float*)d_in[1];
    float*       out     = (float*)d_out;

    const int n_elems = in_sizes[0];
    const int n_rows  = n_elems / T_STEPS;   // 131072

    zero_out_kernel<<<1, 1>>>(out);

    // 2048 blocks x 8 warps = 16384 warps -> 8 rows/warp, 2048 atomics total
    spike_loss_kernel<<<2048, 256>>>(outputs, target, out, n_rows);
}

// round 7
// speedup vs baseline: 1.4542x; 1.4542x over previous
#include <cuda_runtime.h>

// SpikeLoss: delta = outputs - psp(target, tau=5); loss = 0.5*sum(delta^2)
// psp: syn_t = decay*syn_{t-1} + x_t ; y_t = syn_t/tau, scan over T=100
// (contiguous last axis). Row = 100 floats = 400 B = 25 float4, 16B-aligned.
//
// One warp per row (grid-stride, 2 rows/iter). Lane l<25 owns elements
// [4l,4l+4) via a single LDG.128 per tensor. Hybrid scan:
//   1) local serial scan of 4 elems (3 fma)
//   2) Kogge-Stone inclusive scan across lanes of the lane-total with
//      multiplier decay^4 (5 shfl + 5 fma)
//   3) shfl_up(1) -> exclusive carry; apply decay^(j+1)*carry (4 fma)
// Accumulation is PREDICATED on lane<25: lanes >=25 receive nonzero scan
// carries (tv=0 but carry!=0) and must not contribute to the loss.

static constexpr int   T_STEPS = 100;
static constexpr float DECAY   = 0.8f;
static constexpr float INV_TAU = 0.2f;

// decay^4 powers for the Kogge-Stone lane scan
static constexpr float D4  = 0.4096f;                 // 0.8^4
static constexpr float D8  = D4 * D4;                 // 0.8^8
static constexpr float D16 = D8 * D8;
static constexpr float D32 = D16 * D16;
static constexpr float D64 = D32 * D32;

__device__ __forceinline__ float row_pass(float4 tv, float4 ov, int lane, bool ok) {
    // 1) local inclusive scan
    float s0 = tv.x;
    float s1 = fmaf(DECAY, s0, tv.y);
    float s2 = fmaf(DECAY, s1, tv.z);
    float s3 = fmaf(DECAY, s2, tv.w);

    // 2) Kogge-Stone over lane totals, recurrence S_l = D4*S_{l-1} + s3_l
    float v = s3, u;
    u = __shfl_up_sync(0xffffffffu, v, 1);
    if (lane >= 1)  v = fmaf(D4,  u, v);
    u = __shfl_up_sync(0xffffffffu, v, 2);
    if (lane >= 2)  v = fmaf(D8,  u, v);
    u = __shfl_up_sync(0xffffffffu, v, 4);
    if (lane >= 4)  v = fmaf(D16, u, v);
    u = __shfl_up_sync(0xffffffffu, v, 8);
    if (lane >= 8)  v = fmaf(D32, u, v);
    u = __shfl_up_sync(0xffffffffu, v, 16);
    if (lane >= 16) v = fmaf(D64, u, v);

    // 3) exclusive carry into this lane
    float carry = __shfl_up_sync(0xffffffffu, v, 1);
    if (lane == 0) carry = 0.0f;

    s0 = fmaf(0.8f,    carry, s0);
    s1 = fmaf(0.64f,   carry, s1);
    s2 = fmaf(0.512f,  carry, s2);
    s3 = fmaf(0.4096f, carry, s3);

    // delta^2 accumulate — ONLY for the 25 valid lanes
    float acc = 0.0f;
    if (ok) {
        float d;
        d = fmaf(-INV_TAU, s0, ov.x); acc = fmaf(d, d, acc);
        d = fmaf(-INV_TAU, s1, ov.y); acc = fmaf(d, d, acc);
        d = fmaf(-INV_TAU, s2, ov.z); acc = fmaf(d, d, acc);
        d = fmaf(-INV_TAU, s3, ov.w); acc = fmaf(d, d, acc);
    }
    return acc;
}

__global__ __launch_bounds__(256)
void spike_loss_kernel(const float* __restrict__ outputs,
                       const float* __restrict__ target,
                       float* __restrict__ out,
                       int n_rows) {
    const int lane   = threadIdx.x & 31;
    const int wid    = threadIdx.x >> 5;
    const int gwarp  = blockIdx.x * (blockDim.x >> 5) + wid;
    const int nwarps = gridDim.x * (blockDim.x >> 5);

    const bool ok = (lane < 25);
    const float4 zero4 = make_float4(0.f, 0.f, 0.f, 0.f);

    float acc = 0.0f;

    // 2 rows per iteration for MLP (4 independent LDG.128 in flight)
    int row = gwarp * 2;
    const int stride = nwarps * 2;
    for (; row + 1 < n_rows; row += stride) {
        const float4* __restrict__ tr0 =
            reinterpret_cast<const float4*>(target  + (size_t)row * T_STEPS);
        const float4* __restrict__ or0 =
            reinterpret_cast<const float4*>(outputs + (size_t)row * T_STEPS);
        const float4* __restrict__ tr1 =
            reinterpret_cast<const float4*>(target  + (size_t)(row + 1) * T_STEPS);
        const float4* __restrict__ or1 =
            reinterpret_cast<const float4*>(outputs + (size_t)(row + 1) * T_STEPS);

        float4 t0 = ok ? tr0[lane] : zero4;
        float4 o0 = ok ? or0[lane] : zero4;
        float4 t1 = ok ? tr1[lane] : zero4;
        float4 o1 = ok ? or1[lane] : zero4;

        acc += row_pass(t0, o0, lane, ok);
        acc += row_pass(t1, o1, lane, ok);
    }
    for (; row < n_rows; ++row) {
        const float4* __restrict__ tr0 =
            reinterpret_cast<const float4*>(target  + (size_t)row * T_STEPS);
        const float4* __restrict__ or0 =
            reinterpret_cast<const float4*>(outputs + (size_t)row * T_STEPS);
        float4 t0 = ok ? tr0[lane] : zero4;
        float4 o0 = ok ? or0[lane] : zero4;
        acc += row_pass(t0, o0, lane, ok);
    }

    // Warp reduction
    #pragma unroll
    for (int off = 16; off > 0; off >>= 1)
        acc += __shfl_down_sync(0xffffffffu, acc, off);

    __shared__ float warp_sums[8];
    if (lane == 0) warp_sums[wid] = acc;
    __syncthreads();

    if (wid == 0) {
        acc = (lane < (blockDim.x >> 5)) ? warp_sums[lane] : 0.0f;
        #pragma unroll
        for (int off = 4; off > 0; off >>= 1)
            acc += __shfl_down_sync(0xffffffffu, acc, off);
        if (lane == 0)
            atomicAdd(out, 0.5f * acc);
    }
}

extern "C" void kernel_launch(void* const* d_in, const int* in_sizes, int n_in,
                              void* d_out, int out_size) {
    const float* outputs = (const float*)d_in[0];
    const float* target  = (const float*)d_in[1];
    float*       out     = (float*)d_out;

    const int n_elems = in_sizes[0];
    const int n_rows  = n_elems / T_STEPS;   // 131072

    cudaMemsetAsync(out, 0, sizeof(float));

    // 2048 blocks x 8 warps = 16384 warps -> 8 rows/warp (4 iters of 2)
    spike_loss_kernel<<<2048, 256>>>(outputs, target, out, n_rows);
}